// round 3
// baseline (speedup 1.0000x reference)
// ColdDiffusion q_sample with anchor matching — Round 3.
// scan: fp32x2 halves carry TWO POINTS (anchor broadcast from SMEM), 4 packed
//       chains/thread (PPT=8). FMA chain per point bit-identical to reference
//       order. Fold via red.max.u64 on ~(sortable_score,idx) whose identity is
//       0 == zero-initialized global (no init kernel; finalize self-cleans).
// finalize: unpack winner, gather anchor, blend (reference rounding order),
//       reset g_best for the next graph replay.
#include <cuda_runtime.h>

#define D        8
#define M_ANCH   8192
#define BQ       16
#define NQ       2048
#define P_TOTAL  (BQ * NQ)          // 32768 points
#define CHUNK    256                // anchors per CTA chunk
#define NCHUNK   (M_ANCH / CHUNK)   // 32
#define TPB      128                // threads per CTA
#define NCHAIN   4                  // packed point-pair chains per thread
#define PPT      (2 * NCHAIN)       // 8 points per thread
#define PPC      (TPB * PPT)        // 1024 points per CTA
#define NPG      (P_TOTAL / PPC)    // 32 point groups
#define ASTRIDE  10                 // u64 per anchor in smem (8 dims + norm + pad)
#define FLT_BIG  3.402823466e38f

typedef unsigned long long u64;

// Per-point best ~((sortable_score<<32)|idx); MAX == reference argmin with
// first-index ties. Identity 0 == static zero-init; finalize rewrites 0.
__device__ u64 g_best[P_TOTAL];

__device__ __forceinline__ u64 pack2(float lo, float hi) {
    u64 r; asm("mov.b64 %0, {%1,%2};" : "=l"(r) : "f"(lo), "f"(hi)); return r;
}
__device__ __forceinline__ void unpack2(u64 v, float& lo, float& hi) {
    asm("mov.b64 {%0,%1}, %2;" : "=f"(lo), "=f"(hi) : "l"(v));
}
// Packed fp32x2 FMA (SASS FFMA2) — per-half round-to-nearest, bitwise identical
// to scalar FFMA per lane.
__device__ __forceinline__ u64 fma2(u64 a, u64 b, u64 c) {
    u64 d; asm("fma.rn.f32x2 %0, %1, %2, %3;" : "=l"(d) : "l"(a), "l"(b), "l"(c)); return d;
}
// Monotone float -> uint map (total order preserved; no NaNs in this data).
__device__ __forceinline__ unsigned sortable(float f) {
    unsigned u = __float_as_uint(f);
    return (u & 0x80000000u) ? ~u : (u | 0x80000000u);
}

__global__ __launch_bounds__(TPB) void scan_kernel(const float* __restrict__ x,
                                                   const float* __restrict__ anchors) {
    // s_a[j*10 + k] = (a_j[k], a_j[k]) broadcast pairs, k-major; [j*10+8] = (n_j, n_j)
    __shared__ __align__(16) u64 s_a[CHUNK * ASTRIDE];

    const int tid   = threadIdx.x;
    const int pg    = blockIdx.x % NPG;
    const int ch    = blockIdx.x / NPG;
    const int abase = ch * CHUNK;

    // ---- broadcast-pack this chunk's anchors into SMEM ----
    const float* A = anchors + (size_t)abase * D;
    for (int i = tid; i < CHUNK * D; i += TPB) {
        int j = i >> 3, k = i & 7;
        float v = A[i];
        s_a[j * ASTRIDE + k] = pack2(v, v);
    }
    // norms: sequential sum of individually-rounded squares (reference order)
    for (int j = tid; j < CHUNK; j += TPB) {
        const float* a = A + j * D;
        float n = __fmul_rn(a[0], a[0]);
        #pragma unroll
        for (int k = 1; k < D; k++) n = __fadd_rn(n, __fmul_rn(a[k], a[k]));
        s_a[j * ASTRIDE + 8] = pack2(n, n);
    }
    __syncthreads();

    // ---- 8 points per thread as 4 (lo,hi) packed chains ----
    const int base = pg * PPC;
    u64 xx[NCHAIN][D];
    int pLo[NCHAIN], pHi[NCHAIN];
    #pragma unroll
    for (int c = 0; c < NCHAIN; c++) {
        pLo[c] = base + c * TPB + tid;
        pHi[c] = base + (c + NCHAIN) * TPB + tid;
        const float4* xl = (const float4*)(x + (size_t)pLo[c] * D);
        const float4* xh = (const float4*)(x + (size_t)pHi[c] * D);
        float4 l0 = xl[0], l1 = xl[1];
        float4 h0 = xh[0], h1 = xh[1];
        xx[c][0] = pack2(l0.x, h0.x); xx[c][1] = pack2(l0.y, h0.y);
        xx[c][2] = pack2(l0.z, h0.z); xx[c][3] = pack2(l0.w, h0.w);
        xx[c][4] = pack2(l1.x, h1.x); xx[c][5] = pack2(l1.y, h1.y);
        xx[c][6] = pack2(l1.z, h1.z); xx[c][7] = pack2(l1.w, h1.w);
    }
    const u64 NEG2 = pack2(-2.0f, -2.0f);

    float bestLo[NCHAIN], bestHi[NCHAIN];
    int   idxLo[NCHAIN],  idxHi[NCHAIN];
    #pragma unroll
    for (int c = 0; c < NCHAIN; c++) {
        bestLo[c] = FLT_BIG; bestHi[c] = FLT_BIG;
        idxLo[c] = 0; idxHi[c] = 0;
    }

    #pragma unroll 2
    for (int j = 0; j < CHUNK; j++) {
        const u64* ap = s_a + j * ASTRIDE;
        const ulonglong2 q0 = ((const ulonglong2*)ap)[0];
        const ulonglong2 q1 = ((const ulonglong2*)ap)[1];
        const ulonglong2 q2 = ((const ulonglong2*)ap)[2];
        const ulonglong2 q3 = ((const ulonglong2*)ap)[3];
        const u64 nrm = ap[8];
        const int aj = abase + j;

        #pragma unroll
        for (int c = 0; c < NCHAIN; c++) {
            // dot = sum_k x_k*a_k, ascending-k sequential FMA chain per half
            // (reference order for each point independently)
            u64 acc = fma2(xx[c][0], q0.x, 0ull);
            acc = fma2(xx[c][1], q0.y, acc);
            acc = fma2(xx[c][2], q1.x, acc);
            acc = fma2(xx[c][3], q1.y, acc);
            acc = fma2(xx[c][4], q2.x, acc);
            acc = fma2(xx[c][5], q2.y, acc);
            acc = fma2(xx[c][6], q3.x, acc);
            acc = fma2(xx[c][7], q3.y, acc);
            // score = fma(dot,-2,norm): exact pow2 scale => reference rounding
            u64 s2 = fma2(acc, NEG2, nrm);
            float sLo, sHi; unpack2(s2, sLo, sHi);
            // strict < with ascending j == first-index tiebreak
            bool uLo = sLo < bestLo[c];
            bool uHi = sHi < bestHi[c];
            bestLo[c] = uLo ? sLo : bestLo[c];
            idxLo[c]  = uLo ? aj  : idxLo[c];
            bestHi[c] = uHi ? sHi : bestHi[c];
            idxHi[c]  = uHi ? aj  : idxHi[c];
        }
    }

    // fold this chunk's winners into the global per-point best (max-identity 0)
    #pragma unroll
    for (int c = 0; c < NCHAIN; c++) {
        u64 kLo = ~(((u64)sortable(bestLo[c]) << 32) | (unsigned)idxLo[c]);
        u64 kHi = ~(((u64)sortable(bestHi[c]) << 32) | (unsigned)idxHi[c]);
        atomicMax(&g_best[pLo[c]], kLo);
        atomicMax(&g_best[pHi[c]], kHi);
    }
}

__global__ __launch_bounds__(128) void finalize_kernel(const float* __restrict__ x,
                                                       const float* __restrict__ anchors,
                                                       const float* __restrict__ sa_tab,
                                                       const float* __restrict__ sb_tab,
                                                       const int* __restrict__ t,
                                                       float* __restrict__ out) {
    const int point = blockIdx.x * blockDim.x + threadIdx.x;
    if (point >= P_TOTAL) return;

    const int bidx = (int)(unsigned)(~g_best[point] & 0xFFFFFFFFull);
    g_best[point] = 0ull;   // self-clean for the next graph replay

    const int b  = point / NQ;
    const int tb = t[b];
    const float sa = sa_tab[tb];
    const float sb = sb_tab[tb];

    const float4* xp = (const float4*)(x + (size_t)point * D);
    const float4* ap = (const float4*)(anchors + (size_t)bidx * D);
    float4 x0 = xp[0], x1 = xp[1];
    float4 a0 = ap[0], a1 = ap[1];
    float4 o0, o1;
    // out = round(sa*x) + round(sb*a), no FMA contraction (reference order)
    o0.x = __fadd_rn(__fmul_rn(sa, x0.x), __fmul_rn(sb, a0.x));
    o0.y = __fadd_rn(__fmul_rn(sa, x0.y), __fmul_rn(sb, a0.y));
    o0.z = __fadd_rn(__fmul_rn(sa, x0.z), __fmul_rn(sb, a0.z));
    o0.w = __fadd_rn(__fmul_rn(sa, x0.w), __fmul_rn(sb, a0.w));
    o1.x = __fadd_rn(__fmul_rn(sa, x1.x), __fmul_rn(sb, a1.x));
    o1.y = __fadd_rn(__fmul_rn(sa, x1.y), __fmul_rn(sb, a1.y));
    o1.z = __fadd_rn(__fmul_rn(sa, x1.z), __fmul_rn(sb, a1.z));
    o1.w = __fadd_rn(__fmul_rn(sa, x1.w), __fmul_rn(sb, a1.w));

    float4* op = (float4*)(out + (size_t)point * D);
    op[0] = o0; op[1] = o1;
}

extern "C" void kernel_launch(void* const* d_in, const int* in_sizes, int n_in,
                              void* d_out, int out_size) {
    const float* x       = (const float*)d_in[0];  // [16,2048,4,2]
    const float* anchors = (const float*)d_in[1];  // [8192,4,2]
    const float* sa_tab  = (const float*)d_in[2];  // [1000]
    const float* sb_tab  = (const float*)d_in[3];  // [1000]
    const int*   t       = (const int*)d_in[4];    // [16]
    float*       out     = (float*)d_out;          // [16,2048,4,2]

    scan_kernel<<<NPG * NCHUNK, TPB>>>(x, anchors);
    finalize_kernel<<<P_TOTAL / 128, 128>>>(x, anchors, sa_tab, sb_tab, t, out);
}

// round 4
// speedup vs baseline: 1.0153x; 1.0153x over previous
// ColdDiffusion q_sample with anchor matching — Round 4.
// scan: point-pair fp32x2 packing (4 chains = 8 points/thread), anchor
//       register double-buffering to hide LDS latency in-warp, and
//       __launch_bounds__(128,4) to hold 4 CTAs/SM (16 warps).
//       FMA chain per point bit-identical to reference rounding order.
// fold: red.max.u64 on ~(sortable_score,idx); identity 0 == zero-init global;
//       finalize self-cleans for graph replay.
#include <cuda_runtime.h>

#define D        8
#define M_ANCH   8192
#define BQ       16
#define NQ       2048
#define P_TOTAL  (BQ * NQ)          // 32768 points
#define CHUNK    256                // anchors per CTA chunk
#define NCHUNK   (M_ANCH / CHUNK)   // 32
#define TPB      128                // threads per CTA
#define NCHAIN   4                  // packed point-pair chains per thread
#define PPT      (2 * NCHAIN)       // 8 points per thread
#define PPC      (TPB * PPT)        // 1024 points per CTA
#define NPG      (P_TOTAL / PPC)    // 32 point groups
#define ASTRIDE  10                 // u64 per anchor row (8 dims + norm + pad)
#define FLT_BIG  3.402823466e38f

typedef unsigned long long u64;

// Per-point best ~((sortable_score<<32)|idx); MAX == reference argmin with
// first-index ties. Identity 0 == static zero-init; finalize rewrites 0.
__device__ u64 g_best[P_TOTAL];

__device__ __forceinline__ u64 pack2(float lo, float hi) {
    u64 r; asm("mov.b64 %0, {%1,%2};" : "=l"(r) : "f"(lo), "f"(hi)); return r;
}
__device__ __forceinline__ void unpack2(u64 v, float& lo, float& hi) {
    asm("mov.b64 {%0,%1}, %2;" : "=f"(lo), "=f"(hi) : "l"(v));
}
// Packed fp32x2 FMA (SASS FFMA2) — per-half round-to-nearest, bitwise identical
// to scalar FFMA per lane.
__device__ __forceinline__ u64 fma2(u64 a, u64 b, u64 c) {
    u64 d; asm("fma.rn.f32x2 %0, %1, %2, %3;" : "=l"(d) : "l"(a), "l"(b), "l"(c)); return d;
}
// Monotone float -> uint map (total order preserved; no NaNs in this data).
__device__ __forceinline__ unsigned sortable(float f) {
    unsigned u = __float_as_uint(f);
    return (u & 0x80000000u) ? ~u : (u | 0x80000000u);
}

__global__ __launch_bounds__(TPB, 4) void scan_kernel(const float* __restrict__ x,
                                                      const float* __restrict__ anchors) {
    // s_a[j*10 + k] = (a_j[k], a_j[k]) broadcast pairs, k-major; [j*10+8] = (n_j, n_j)
    // +1 guard row so the prefetch of j==CHUNK stays in-bounds (value unused).
    __shared__ __align__(16) u64 s_a[(CHUNK + 1) * ASTRIDE];

    const int tid   = threadIdx.x;
    const int pg    = blockIdx.x % NPG;
    const int ch    = blockIdx.x / NPG;
    const int abase = ch * CHUNK;

    // ---- broadcast-pack this chunk's anchors into SMEM ----
    const float* A = anchors + (size_t)abase * D;
    for (int i = tid; i < CHUNK * D; i += TPB) {
        int j = i >> 3, k = i & 7;
        float v = A[i];
        s_a[j * ASTRIDE + k] = pack2(v, v);
    }
    // norms: sequential sum of individually-rounded squares (reference order)
    for (int j = tid; j < CHUNK; j += TPB) {
        const float* a = A + j * D;
        float n = __fmul_rn(a[0], a[0]);
        #pragma unroll
        for (int k = 1; k < D; k++) n = __fadd_rn(n, __fmul_rn(a[k], a[k]));
        s_a[j * ASTRIDE + 8] = pack2(n, n);
    }
    if (tid < ASTRIDE) s_a[CHUNK * ASTRIDE + tid] = 0ull;  // guard row
    __syncthreads();

    // ---- 8 points per thread as 4 (lo,hi) packed chains ----
    const int base = pg * PPC;
    u64 xx[NCHAIN][D];
    int pLo[NCHAIN], pHi[NCHAIN];
    #pragma unroll
    for (int c = 0; c < NCHAIN; c++) {
        pLo[c] = base + c * TPB + tid;
        pHi[c] = base + (c + NCHAIN) * TPB + tid;
        const float4* xl = (const float4*)(x + (size_t)pLo[c] * D);
        const float4* xh = (const float4*)(x + (size_t)pHi[c] * D);
        float4 l0 = xl[0], l1 = xl[1];
        float4 h0 = xh[0], h1 = xh[1];
        xx[c][0] = pack2(l0.x, h0.x); xx[c][1] = pack2(l0.y, h0.y);
        xx[c][2] = pack2(l0.z, h0.z); xx[c][3] = pack2(l0.w, h0.w);
        xx[c][4] = pack2(l1.x, h1.x); xx[c][5] = pack2(l1.y, h1.y);
        xx[c][6] = pack2(l1.z, h1.z); xx[c][7] = pack2(l1.w, h1.w);
    }
    const u64 NEG2 = pack2(-2.0f, -2.0f);

    float bestLo[NCHAIN], bestHi[NCHAIN];
    int   idxLo[NCHAIN],  idxHi[NCHAIN];
    #pragma unroll
    for (int c = 0; c < NCHAIN; c++) {
        bestLo[c] = FLT_BIG; bestHi[c] = FLT_BIG;
        idxLo[c] = 0; idxHi[c] = 0;
    }

    // register double-buffer: prefetch anchor j+1 while computing anchor j
    ulonglong2 q0 = ((const ulonglong2*)s_a)[0];
    ulonglong2 q1 = ((const ulonglong2*)s_a)[1];
    ulonglong2 q2 = ((const ulonglong2*)s_a)[2];
    ulonglong2 q3 = ((const ulonglong2*)s_a)[3];
    u64        nrm = s_a[8];

    #pragma unroll 2
    for (int j = 0; j < CHUNK; j++) {
        const u64* np = s_a + (j + 1) * ASTRIDE;     // guard row makes j+1 safe
        ulonglong2 t0 = ((const ulonglong2*)np)[0];
        ulonglong2 t1 = ((const ulonglong2*)np)[1];
        ulonglong2 t2 = ((const ulonglong2*)np)[2];
        ulonglong2 t3 = ((const ulonglong2*)np)[3];
        u64        tn = np[8];

        #pragma unroll
        for (int c = 0; c < NCHAIN; c++) {
            // dot = sum_k x_k*a_k, ascending-k sequential FMA chain per half
            // (reference order for each point independently)
            u64 acc = fma2(xx[c][0], q0.x, 0ull);
            acc = fma2(xx[c][1], q0.y, acc);
            acc = fma2(xx[c][2], q1.x, acc);
            acc = fma2(xx[c][3], q1.y, acc);
            acc = fma2(xx[c][4], q2.x, acc);
            acc = fma2(xx[c][5], q2.y, acc);
            acc = fma2(xx[c][6], q3.x, acc);
            acc = fma2(xx[c][7], q3.y, acc);
            // score = fma(dot,-2,norm): exact pow2 scale => reference rounding
            u64 s2 = fma2(acc, NEG2, nrm);
            float sLo, sHi; unpack2(s2, sLo, sHi);
            // strict < with ascending j == first-index tiebreak
            bool uLo = sLo < bestLo[c];
            bool uHi = sHi < bestHi[c];
            bestLo[c] = uLo ? sLo : bestLo[c];
            idxLo[c]  = uLo ? j   : idxLo[c];
            bestHi[c] = uHi ? sHi : bestHi[c];
            idxHi[c]  = uHi ? j   : idxHi[c];
        }

        q0 = t0; q1 = t1; q2 = t2; q3 = t3; nrm = tn;
    }

    // fold this chunk's winners into the global per-point best (max-identity 0)
    #pragma unroll
    for (int c = 0; c < NCHAIN; c++) {
        u64 kLo = ~(((u64)sortable(bestLo[c]) << 32) | (unsigned)(abase + idxLo[c]));
        u64 kHi = ~(((u64)sortable(bestHi[c]) << 32) | (unsigned)(abase + idxHi[c]));
        atomicMax(&g_best[pLo[c]], kLo);
        atomicMax(&g_best[pHi[c]], kHi);
    }
}

__global__ __launch_bounds__(128) void finalize_kernel(const float* __restrict__ x,
                                                       const float* __restrict__ anchors,
                                                       const float* __restrict__ sa_tab,
                                                       const float* __restrict__ sb_tab,
                                                       const int* __restrict__ t,
                                                       float* __restrict__ out) {
    const int point = blockIdx.x * blockDim.x + threadIdx.x;
    if (point >= P_TOTAL) return;

    const int bidx = (int)(unsigned)(~g_best[point] & 0xFFFFFFFFull);
    g_best[point] = 0ull;   // self-clean for the next graph replay

    const int b  = point / NQ;
    const int tb = t[b];
    const float sa = sa_tab[tb];
    const float sb = sb_tab[tb];

    const float4* xp = (const float4*)(x + (size_t)point * D);
    const float4* ap = (const float4*)(anchors + (size_t)bidx * D);
    float4 x0 = xp[0], x1 = xp[1];
    float4 a0 = ap[0], a1 = ap[1];
    float4 o0, o1;
    // out = round(sa*x) + round(sb*a), no FMA contraction (reference order)
    o0.x = __fadd_rn(__fmul_rn(sa, x0.x), __fmul_rn(sb, a0.x));
    o0.y = __fadd_rn(__fmul_rn(sa, x0.y), __fmul_rn(sb, a0.y));
    o0.z = __fadd_rn(__fmul_rn(sa, x0.z), __fmul_rn(sb, a0.z));
    o0.w = __fadd_rn(__fmul_rn(sa, x0.w), __fmul_rn(sb, a0.w));
    o1.x = __fadd_rn(__fmul_rn(sa, x1.x), __fmul_rn(sb, a1.x));
    o1.y = __fadd_rn(__fmul_rn(sa, x1.y), __fmul_rn(sb, a1.y));
    o1.z = __fadd_rn(__fmul_rn(sa, x1.z), __fmul_rn(sb, a1.z));
    o1.w = __fadd_rn(__fmul_rn(sa, x1.w), __fmul_rn(sb, a1.w));

    float4* op = (float4*)(out + (size_t)point * D);
    op[0] = o0; op[1] = o1;
}

extern "C" void kernel_launch(void* const* d_in, const int* in_sizes, int n_in,
                              void* d_out, int out_size) {
    const float* x       = (const float*)d_in[0];  // [16,2048,4,2]
    const float* anchors = (const float*)d_in[1];  // [8192,4,2]
    const float* sa_tab  = (const float*)d_in[2];  // [1000]
    const float* sb_tab  = (const float*)d_in[3];  // [1000]
    const int*   t       = (const int*)d_in[4];    // [16]
    float*       out     = (float*)d_out;          // [16,2048,4,2]

    scan_kernel<<<NPG * NCHUNK, TPB>>>(x, anchors);
    finalize_kernel<<<P_TOTAL / 128, 128>>>(x, anchors, sa_tab, sb_tab, t, out);
}